// round 15
// baseline (speedup 1.0000x reference)
#include <cuda_runtime.h>
#include <cuda_fp16.h>
#include <math.h>
#include <cstdint>

// Problem constants
#define Bb   4
#define Tt   4096
#define Dd   1024
#define Hh   16
#define DH   64
#define Mm   (Bb*Tt)          // 16384 rows
#define NELEM (Mm*Dd)
#define CCH  8                // ctx T-chunks

// ---------------- scratch (device globals; no allocation allowed) -------------
__device__ __half g_xnh[NELEM];           // ln1 out, fp16, pair-permuted
__device__ __half g_hh [NELEM];           // ln2 out, fp16, pair-permuted
__device__ __half g_wth[4*Dd*Dd];         // Wq|Wk|Wv|out_W transposed, fp16, pair-permuted
__device__ __half g_q  [NELEM];
__device__ __half g_k  [NELEM];
__device__ __half g_v  [NELEM];
__device__ __half g_y  [NELEM];
__device__ float g_ctxp[CCH*Bb*Hh*DH*DH];
__device__ float g_cm [CCH*Bb*Hh*DH];
__device__ float g_cs [CCH*Bb*Hh*DH];
__device__ float g_ctx[Bb*Hh*DH*DH];
__device__ float g_ss [Bb*2*Dd];

__host__ __device__ __forceinline__ int pos16(int k) {
    int p = (k >> 1) & 7;
    int slot = 2 * (p & 3) + (p >> 2);
    return (k & ~15) | (slot * 2) | (k & 1);
}

// ---------------- helpers ----------------
__device__ __forceinline__ float warpSum(float v) {
    #pragma unroll
    for (int o = 16; o > 0; o >>= 1) v += __shfl_xor_sync(0xffffffffu, v, o);
    return v;
}
__device__ __forceinline__ float siluf(float v) { return v / (1.0f + __expf(-v)); }

#define CP_ASYNC16(dst, src) \
    asm volatile("cp.async.cg.shared.global [%0], [%1], 16;" :: "r"(dst), "l"(src))
#define CP_COMMIT() asm volatile("cp.async.commit_group;" ::: "memory")
#define CP_WAIT(n)  asm volatile("cp.async.wait_group %0;" :: "n"(n) : "memory")

__device__ __forceinline__ uint32_t smem_u32(const void* p) {
    uint32_t a;
    asm("{ .reg .u64 t; cvta.to.shared.u64 t, %1; cvt.u32.u64 %0, t; }" : "=r"(a) : "l"(p));
    return a;
}

__device__ __forceinline__ void lds64(uint32_t addr, uint32_t& r0, uint32_t& r1) {
    asm volatile("ld.shared.v2.b32 {%0,%1}, [%2];" : "=r"(r0), "=r"(r1) : "r"(addr));
}

__device__ __forceinline__ void mma_fp16(float* c, uint32_t a0, uint32_t a1, uint32_t a2,
                                         uint32_t a3, uint32_t b0, uint32_t b1) {
    asm volatile(
        "mma.sync.aligned.m16n8k16.row.col.f32.f16.f16.f32 "
        "{%0,%1,%2,%3}, {%4,%5,%6,%7}, {%8,%9}, {%0,%1,%2,%3};"
        : "+f"(c[0]), "+f"(c[1]), "+f"(c[2]), "+f"(c[3])
        : "r"(a0), "r"(a1), "r"(a2), "r"(a3), "r"(b0), "r"(b1));
}

// ================= fp16 GEMM core constants =================
#define BM 128
#define BN 128
#define BKB 64
#define LDB 80
#define BSTGB (BM*LDB)
#define NITB (Dd/BKB)
#define GSMEM 81920

// ================= fp16 fused QKV GEMM (fp16 outputs) =================
__global__ void __launch_bounds__(256, 2)
qkv_gemm(const __half* __restrict__ A, const __half* __restrict__ Bt,
         const float* __restrict__ bias_q, const float* __restrict__ bias_k,
         const float* __restrict__ bias_v,
         __half* __restrict__ Cq, __half* __restrict__ Ck, __half* __restrict__ Cv)
{
    extern __shared__ float sm[];

    const int tid  = threadIdx.x;
    const int wid  = tid >> 5;
    const int lane = tid & 31;
    const int g    = lane >> 2;
    const int tig  = lane & 3;
    const int wm   = wid >> 1;
    const int wn   = wid & 1;
    const int cRow = blockIdx.y * BM;

    const int sel = blockIdx.x >> 3;
    const float* bias = (sel == 0) ? bias_q : (sel == 1) ? bias_k : bias_v;
    __half* C         = (sel == 0) ? Cq     : (sel == 1) ? Ck     : Cv;
    const int cCol = (blockIdx.x & 7) * BN;

    const int prow = tid >> 3;
    const int pch  = tid & 7;
    const uint32_t smBase = smem_u32(sm);
    const uint32_t sA0 = smBase + (uint32_t)(prow * LDB + pch * 8) * 2;
    const uint32_t sB0 = sA0 + 2u * BSTGB * 2;
    const __half* gA = A  + (size_t)(cRow + prow) * Dd + pch * 8;
    const __half* gB = Bt + (size_t)(blockIdx.x * BN + prow) * Dd + pch * 8;

    #define LOAD_STAGE(it) do { \
        int _s = (it) & 1; int _k0 = (it) * BKB; \
        uint32_t _sa = sA0 + (uint32_t)(_s * BSTGB) * 2; \
        uint32_t _sb = sB0 + (uint32_t)(_s * BSTGB) * 2; \
        _Pragma("unroll") \
        for (int _p = 0; _p < 4; _p++) { \
            CP_ASYNC16(_sa + _p * 32 * LDB * 2, gA + (size_t)_p * 32 * Dd + _k0); \
            CP_ASYNC16(_sb + _p * 32 * LDB * 2, gB + (size_t)_p * 32 * Dd + _k0); \
        } \
        CP_COMMIT(); \
    } while (0)

    LOAD_STAGE(0);

    float acc[2][8][4] = {};

    const uint32_t aW = smBase + (uint32_t)((wm*32 + g) * LDB) * 2 + tig * 8;
    const uint32_t bW = smBase + (uint32_t)(2 * BSTGB + (wn*64 + g) * LDB) * 2 + tig * 8;

    for (int it = 0; it < NITB; ++it) {
        CP_WAIT(0);
        __syncthreads();
        if (it + 1 < NITB) LOAD_STAGE(it + 1);

        const uint32_t so = (uint32_t)((it & 1) * BSTGB * 2);
        const uint32_t aS = aW + so;
        const uint32_t bS = bW + so;
        #pragma unroll
        for (int ks = 0; ks < 4; ks++) {
            const uint32_t kb = ks * 32;
            uint32_t a[2][4];
            lds64(aS + kb,                 a[0][0], a[0][2]);
            lds64(aS + 8*LDB*2 + kb,       a[0][1], a[0][3]);
            lds64(aS + 16*LDB*2 + kb,      a[1][0], a[1][2]);
            lds64(aS + 24*LDB*2 + kb,      a[1][1], a[1][3]);
            #pragma unroll
            for (int nt = 0; nt < 8; nt++) {
                uint32_t b0, b1;
                lds64(bS + nt*8*LDB*2 + kb, b0, b1);
                mma_fp16(acc[0][nt], a[0][0], a[0][1], a[0][2], a[0][3], b0, b1);
                mma_fp16(acc[1][nt], a[1][0], a[1][1], a[1][2], a[1][3], b0, b1);
            }
        }
    }

    #pragma unroll
    for (int mt = 0; mt < 2; mt++) {
        const int r0 = cRow + wm*32 + mt*16 + g;
        const int r1 = r0 + 8;
        #pragma unroll
        for (int nt = 0; nt < 8; nt++) {
            const int c0 = cCol + wn*64 + nt*8 + tig*2;
            float bx = bias[c0], by = bias[c0+1];
            __half2 u0 = __float22half2_rn(make_float2(acc[mt][nt][0] + bx, acc[mt][nt][1] + by));
            __half2 u1 = __float22half2_rn(make_float2(acc[mt][nt][2] + bx, acc[mt][nt][3] + by));
            *(__half2*)(C + (size_t)r0 * Dd + c0) = u0;
            *(__half2*)(C + (size_t)r1 * Dd + c0) = u1;
        }
    }
    #undef LOAD_STAGE
}

// ================= fp16 out-projection GEMM (+ residual epilogue, fp32 out) =================
__global__ void __launch_bounds__(256, 2)
out_gemm(const __half* __restrict__ A, const __half* __restrict__ Bt,
         const float* __restrict__ bias, float* __restrict__ C,
         const float* __restrict__ resid, const float* __restrict__ gate)
{
    extern __shared__ float sm[];

    const int tid  = threadIdx.x;
    const int wid  = tid >> 5;
    const int lane = tid & 31;
    const int g    = lane >> 2;
    const int tig  = lane & 3;
    const int wm   = wid >> 1;
    const int wn   = wid & 1;
    const int cRow = blockIdx.y * BM;
    const int cCol = blockIdx.x * BN;

    const int prow = tid >> 3;
    const int pch  = tid & 7;
    const uint32_t smBase = smem_u32(sm);
    const uint32_t sA0 = smBase + (uint32_t)(prow * LDB + pch * 8) * 2;
    const uint32_t sB0 = sA0 + 2u * BSTGB * 2;
    const __half* gA = A  + (size_t)(cRow + prow) * Dd + pch * 8;
    const __half* gB = Bt + (size_t)(cCol + prow) * Dd + pch * 8;

    #define LOAD_STAGE(it) do { \
        int _s = (it) & 1; int _k0 = (it) * BKB; \
        uint32_t _sa = sA0 + (uint32_t)(_s * BSTGB) * 2; \
        uint32_t _sb = sB0 + (uint32_t)(_s * BSTGB) * 2; \
        _Pragma("unroll") \
        for (int _p = 0; _p < 4; _p++) { \
            CP_ASYNC16(_sa + _p * 32 * LDB * 2, gA + (size_t)_p * 32 * Dd + _k0); \
            CP_ASYNC16(_sb + _p * 32 * LDB * 2, gB + (size_t)_p * 32 * Dd + _k0); \
        } \
        CP_COMMIT(); \
    } while (0)

    LOAD_STAGE(0);

    float acc[2][8][4] = {};

    const uint32_t aW = smBase + (uint32_t)((wm*32 + g) * LDB) * 2 + tig * 8;
    const uint32_t bW = smBase + (uint32_t)(2 * BSTGB + (wn*64 + g) * LDB) * 2 + tig * 8;

    for (int it = 0; it < NITB; ++it) {
        CP_WAIT(0);
        __syncthreads();
        if (it + 1 < NITB) LOAD_STAGE(it + 1);

        const uint32_t so = (uint32_t)((it & 1) * BSTGB * 2);
        const uint32_t aS = aW + so;
        const uint32_t bS = bW + so;
        #pragma unroll
        for (int ks = 0; ks < 4; ks++) {
            const uint32_t kb = ks * 32;
            uint32_t a[2][4];
            lds64(aS + kb,                 a[0][0], a[0][2]);
            lds64(aS + 8*LDB*2 + kb,       a[0][1], a[0][3]);
            lds64(aS + 16*LDB*2 + kb,      a[1][0], a[1][2]);
            lds64(aS + 24*LDB*2 + kb,      a[1][1], a[1][3]);
            #pragma unroll
            for (int nt = 0; nt < 8; nt++) {
                uint32_t b0, b1;
                lds64(bS + nt*8*LDB*2 + kb, b0, b1);
                mma_fp16(acc[0][nt], a[0][0], a[0][1], a[0][2], a[0][3], b0, b1);
                mma_fp16(acc[1][nt], a[1][0], a[1][1], a[1][2], a[1][3], b0, b1);
            }
        }
    }

    const int bb = cRow >> 12;
    #pragma unroll
    for (int mt = 0; mt < 2; mt++) {
        const int r0 = cRow + wm*32 + mt*16 + g;
        const int r1 = r0 + 8;
        #pragma unroll
        for (int nt = 0; nt < 8; nt++) {
            const int c0 = cCol + wn*64 + nt*8 + tig*2;
            float bx = bias[c0], by = bias[c0+1];
            float gx = gate[bb*Dd + c0], gy = gate[bb*Dd + c0 + 1];
            float2 rA = *(const float2*)(resid + (size_t)r0 * Dd + c0);
            float2 rB = *(const float2*)(resid + (size_t)r1 * Dd + c0);
            float2 v0, v1;
            v0.x = rA.x + gx * (acc[mt][nt][0] + bx);
            v0.y = rA.y + gy * (acc[mt][nt][1] + by);
            v1.x = rB.x + gx * (acc[mt][nt][2] + bx);
            v1.y = rB.y + gy * (acc[mt][nt][3] + by);
            *(float2*)(C + (size_t)r0 * Dd + c0) = v0;
            *(float2*)(C + (size_t)r1 * Dd + c0) = v1;
        }
    }
    #undef LOAD_STAGE
}

// ---------------- weight transposes: all 4 -> fp16, pair-permuted ----------------
__global__ __launch_bounds__(256)
void transpose_round4(const float* __restrict__ W0, const float* __restrict__ W1,
                      const float* __restrict__ W2, const float* __restrict__ W3,
                      __half* __restrict__ Wth)
{
    const float* W = (blockIdx.z == 0) ? W0 : (blockIdx.z == 1) ? W1 :
                     (blockIdx.z == 2) ? W2 : W3;
    __half* out = Wth + (size_t)blockIdx.z * Dd * Dd;

    __shared__ float t[32][33];
    int x = blockIdx.x * 32 + threadIdx.x;
    int y = blockIdx.y * 32 + threadIdx.y;
    #pragma unroll
    for (int j = 0; j < 32; j += 8)
        t[threadIdx.y + j][threadIdx.x] = W[(size_t)(y + j) * Dd + x];
    __syncthreads();
    int xo = blockIdx.y * 32 + threadIdx.x;
    int yo = blockIdx.x * 32 + threadIdx.y;
    int xp = pos16(xo);
    #pragma unroll
    for (int j = 0; j < 32; j += 8)
        out[(size_t)(yo + j) * Dd + xp] = __float2half(t[threadIdx.x][threadIdx.y + j]);
}

// ---------------- LayerNorm 1: x -> xn (fp16, pair-permuted store) ----------------
__global__ __launch_bounds__(256)
void ln1_kernel(const float* __restrict__ x, const float* __restrict__ g,
                const float* __restrict__ b, __half* __restrict__ out)
{
    const int row = blockIdx.x;
    const float* xr = x + (size_t)row * Dd;
    float4 xv = *(const float4*)(xr + threadIdx.x * 4);
    float s  = xv.x + xv.y + xv.z + xv.w;
    float s2 = xv.x*xv.x + xv.y*xv.y + xv.z*xv.z + xv.w*xv.w;

    __shared__ float sh1[8], sh2[8], bc[2];
    s = warpSum(s); s2 = warpSum(s2);
    int w = threadIdx.x >> 5;
    if ((threadIdx.x & 31) == 0) { sh1[w] = s; sh2[w] = s2; }
    __syncthreads();
    if (threadIdx.x == 0) {
        float a = 0.f, c = 0.f;
        #pragma unroll
        for (int i = 0; i < 8; i++) { a += sh1[i]; c += sh2[i]; }
        bc[0] = a; bc[1] = c;
    }
    __syncthreads();
    float mu  = bc[0] * (1.0f / Dd);
    float var = bc[1] * (1.0f / Dd) - mu * mu;
    float inv = rsqrtf(var + 1e-5f);

    int d = threadIdx.x * 4;
    float4 gv = *(const float4*)(g + d);
    float4 bv = *(const float4*)(b + d);
    float o0 = (xv.x - mu) * inv * gv.x + bv.x;
    float o1 = (xv.y - mu) * inv * gv.y + bv.y;
    float o2 = (xv.z - mu) * inv * gv.z + bv.z;
    float o3 = (xv.w - mu) * inv * gv.w + bv.w;
    __half2 u0 = __float22half2_rn(make_float2(o0, o1));
    __half2 u1 = __float22half2_rn(make_float2(o2, o3));
    __half* ob = out + (size_t)row * Dd;
    *(__half2*)(ob + pos16(d))     = u0;
    *(__half2*)(ob + pos16(d + 2)) = u1;
}

// ---------------- ctx: online temporal softmax, 8x8 tiles with 4-way t-split --------
__global__ void __launch_bounds__(256, 2)
ctx_kernel(const __half* __restrict__ k, const __half* __restrict__ v,
           float* __restrict__ ctxp, float* __restrict__ cm, float* __restrict__ cs)
{
    int bh = blockIdx.x;
    int b = bh >> 4, h = bh & 15;
    __shared__ float ks[64][64];
    __shared__ float vs[64][64];
    __shared__ float m_sh[64], s_sh[64], f_sh[64];
    __shared__ float part[4][64];

    const int tid = threadIdx.x;
    const int rd  = tid & 63;     // reduction: feature column
    const int qt  = tid >> 6;     // t-quarter 0..3
    const int tt  = tid & 63;     // output tile id
    const int trr = (tt >> 3) * 8;  // d-row base
    const int tcc = (tt & 7) * 8;   // l-col base
    const int t0q = qt * 16;        // this thread's t range within chunk

    if (tid < 64) { m_sh[tid] = -INFINITY; s_sh[tid] = 0.0f; }

    float acc[8][8] = {};
    int tbase = blockIdx.y * (Tt / CCH);
    for (int tt0 = 0; tt0 < Tt / CCH; tt0 += 64) {
        __syncthreads();
        for (int i = tid; i < 64 * 16; i += 256) {
            int t  = i >> 4;
            int c4 = (i & 15) * 4;
            size_t off = ((size_t)((b * Tt + tbase + tt0 + t)) * Hh + h) * DH + c4;
            float2 kraw = *(const float2*)(k + off);
            float2 vraw = *(const float2*)(v + off);
            const __half2* kh = (const __half2*)&kraw;
            const __half2* vh = (const __half2*)&vraw;
            float2 k01 = __half22float2(kh[0]), k23 = __half22float2(kh[1]);
            float2 v01 = __half22float2(vh[0]), v23 = __half22float2(vh[1]);
            ks[t][c4+0] = k01.x; ks[t][c4+1] = k01.y;
            ks[t][c4+2] = k23.x; ks[t][c4+3] = k23.y;
            vs[t][c4+0] = v01.x; vs[t][c4+1] = v01.y;
            vs[t][c4+2] = v23.x; vs[t][c4+3] = v23.y;
        }
        __syncthreads();
        // partial max
        {
            float tm = -INFINITY;
            #pragma unroll
            for (int t = 0; t < 16; t++) tm = fmaxf(tm, ks[qt * 16 + t][rd]);
            part[qt][rd] = tm;
        }
        __syncthreads();
        if (tid < 64) {
            int d = tid;
            float tm = fmaxf(fmaxf(part[0][d], part[1][d]), fmaxf(part[2][d], part[3][d]));
            float mn = fmaxf(m_sh[d], tm);
            f_sh[d] = __expf(m_sh[d] - mn);
            m_sh[d] = mn;
        }
        __syncthreads();
        // fused exponentiate + partial sum
        {
            float md = m_sh[rd];
            float csum = 0.0f;
            #pragma unroll
            for (int t = 0; t < 16; t++) {
                float e = __expf(ks[qt * 16 + t][rd] - md);
                ks[qt * 16 + t][rd] = e;
                csum += e;
            }
            part[qt][rd] = csum;
        }
        __syncthreads();
        if (tid < 64) {
            int d = tid;
            s_sh[d] = s_sh[d] * f_sh[d] +
                      ((part[0][d] + part[1][d]) + (part[2][d] + part[3][d]));
        }
        // rescale accumulator rows by f (chunk-level factor)
        float fr[8];
        #pragma unroll
        for (int i = 0; i < 8; i++) fr[i] = f_sh[trr + i];
        #pragma unroll
        for (int i = 0; i < 8; i++)
            #pragma unroll
            for (int j = 0; j < 8; j++)
                acc[i][j] *= fr[i];
        // accumulate 8x8 outer products over this thread's 16 t-rows
        #pragma unroll 4
        for (int t = t0q; t < t0q + 16; t++) {
            float4 k0 = *(const float4*)&ks[t][trr];
            float4 k1 = *(const float4*)&ks[t][trr + 4];
            float4 v0 = *(const float4*)&vs[t][tcc];
            float4 v1 = *(const float4*)&vs[t][tcc + 4];
            float rk[8] = {k0.x, k0.y, k0.z, k0.w, k1.x, k1.y, k1.z, k1.w};
            float rv[8] = {v0.x, v0.y, v0.z, v0.w, v1.x, v1.y, v1.z, v1.w};
            #pragma unroll
            for (int i = 0; i < 8; i++)
                #pragma unroll
                for (int j = 0; j < 8; j++)
                    acc[i][j] += rk[i] * rv[j];
        }
    }
    __syncthreads();
    // combine 4 t-split partials (fixed order, deterministic): stage qt0/qt1, add qt2/qt3
    if (qt == 0) {
        #pragma unroll
        for (int i = 0; i < 8; i++)
            #pragma unroll
            for (int j = 0; j < 8; j++)
                ks[trr + i][tcc + j] = acc[i][j];
    } else if (qt == 1) {
        #pragma unroll
        for (int i = 0; i < 8; i++)
            #pragma unroll
            for (int j = 0; j < 8; j++)
                vs[trr + i][tcc + j] = acc[i][j];
    }
    __syncthreads();
    if (qt == 2) {
        #pragma unroll
        for (int i = 0; i < 8; i++)
            #pragma unroll
            for (int j = 0; j < 8; j++)
                ks[trr + i][tcc + j] += acc[i][j];
    } else if (qt == 3) {
        #pragma unroll
        for (int i = 0; i < 8; i++)
            #pragma unroll
            for (int j = 0; j < 8; j++)
                vs[trr + i][tcc + j] += acc[i][j];
    }
    __syncthreads();
    float* c = ctxp + (size_t)blockIdx.y * (Bb*Hh*DH*DH) + (size_t)bh * (DH * DH);
    for (int i = tid; i < DH * DH; i += 256)
        c[i] = ks[i >> 6][i & 63] + vs[i >> 6][i & 63];
    if (tid < 64) {
        int idx = blockIdx.y * (Bb*Hh*DH) + bh * DH + tid;
        cm[idx] = m_sh[tid];
        cs[idx] = s_sh[tid];
    }
}

// global combine
__global__ __launch_bounds__(256)
void ctx_reduce(const float* __restrict__ p, const float* __restrict__ cm,
                const float* __restrict__ cs, float* __restrict__ ctx)
{
    int bh = blockIdx.x;
    __shared__ float ef[CCH][64];
    __shared__ float Sinv[64];
    int tid = threadIdx.x;
    if (tid < 64) {
        float mx = -INFINITY;
        #pragma unroll
        for (int c = 0; c < CCH; c++)
            mx = fmaxf(mx, cm[c * (Bb*Hh*DH) + bh * DH + tid]);
        float S = 0.0f;
        #pragma unroll
        for (int c = 0; c < CCH; c++) {
            float e = __expf(cm[c * (Bb*Hh*DH) + bh * DH + tid] - mx);
            ef[c][tid] = e;
            S += cs[c * (Bb*Hh*DH) + bh * DH + tid] * e;
        }
        Sinv[tid] = 1.0f / S;
    }
    __syncthreads();
    for (int i = tid; i < DH * DH; i += 256) {
        int d = i >> 6;
        float s = 0.0f;
        #pragma unroll
        for (int c = 0; c < CCH; c++)
            s += p[(size_t)c * (Bb*Hh*DH*DH) + (size_t)bh * (DH*DH) + i] * ef[c][d];
        ctx[(size_t)bh * (DH*DH) + i] = s * Sinv[d];
    }
}

// ---------------- y = softmax(q) @ ctx  (fp16 q in, fp16 y out) ----------------
__global__ __launch_bounds__(256)
void y_kernel(const __half* __restrict__ q, const float* __restrict__ ctx,
              __half* __restrict__ y)
{
    int bh = blockIdx.x;
    int b = bh >> 4, h = bh & 15;
    __shared__ float cs[DH * DH];
    for (int i = threadIdx.x; i < 1024; i += 256)
        *(float4*)&cs[i * 4] = *(const float4*)(ctx + (size_t)bh * (DH * DH) + i * 4);
    __syncthreads();

    int t = blockIdx.y * 256 + threadIdx.x;
    size_t off = ((size_t)(b * Tt + t) * Hh + h) * DH;
    const float4* qr4 = (const float4*)(q + off);

    float4 qv[16];
    #pragma unroll
    for (int j = 0; j < 8; j++) {
        float4 raw = qr4[j];
        const __half2* hp = (const __half2*)&raw;
        float2 a = __half22float2(hp[0]), bb2 = __half22float2(hp[1]);
        float2 c = __half22float2(hp[2]), dd2 = __half22float2(hp[3]);
        qv[2*j]   = make_float4(a.x, a.y, bb2.x, bb2.y);
        qv[2*j+1] = make_float4(c.x, c.y, dd2.x, dd2.y);
    }
    float m = -INFINITY;
    #pragma unroll
    for (int j = 0; j < 16; j++)
        m = fmaxf(m, fmaxf(fmaxf(qv[j].x, qv[j].y), fmaxf(qv[j].z, qv[j].w)));
    float sum = 0.f;
    #pragma unroll
    for (int j = 0; j < 16; j++) {
        qv[j].x = __expf(qv[j].x - m); qv[j].y = __expf(qv[j].y - m);
        qv[j].z = __expf(qv[j].z - m); qv[j].w = __expf(qv[j].w - m);
        sum += qv[j].x + qv[j].y + qv[j].z + qv[j].w;
    }
    float sinv = 1.0f / sum;

    float4 acc[16];
    #pragma unroll
    for (int j = 0; j < 16; j++) acc[j] = make_float4(0.f, 0.f, 0.f, 0.f);

    #pragma unroll 4
    for (int j4 = 0; j4 < 16; j4++) {
        int d0 = j4 * 4;
        #pragma unroll
        for (int dd = 0; dd < 4; dd++) {
            float qd = ((dd == 0) ? qv[j4].x : (dd == 1) ? qv[j4].y :
                        (dd == 2) ? qv[j4].z : qv[j4].w) * sinv;
            const float4* crow = (const float4*)(cs + (d0 + dd) * DH);
            #pragma unroll
            for (int j = 0; j < 16; j++) {
                float4 c = crow[j];
                acc[j].x += qd * c.x;
                acc[j].y += qd * c.y;
                acc[j].z += qd * c.z;
                acc[j].w += qd * c.w;
            }
        }
    }
    float4* yr = (float4*)(y + off);
    #pragma unroll
    for (int j = 0; j < 8; j++) {
        float4 raw;
        __half2* hp = (__half2*)&raw;
        hp[0] = __float22half2_rn(make_float2(acc[2*j].x,   acc[2*j].y));
        hp[1] = __float22half2_rn(make_float2(acc[2*j].z,   acc[2*j].w));
        hp[2] = __float22half2_rn(make_float2(acc[2*j+1].x, acc[2*j+1].y));
        hp[3] = __float22half2_rn(make_float2(acc[2*j+1].z, acc[2*j+1].w));
        yr[j] = raw;
    }
}

// ---------------- emb MLP ----------------
__global__ __launch_bounds__(256)
void emb_kernel(const float* __restrict__ emb, const float* __restrict__ W,
                const float* __restrict__ eb, float* __restrict__ ss)
{
    int b = blockIdx.y;
    int n = blockIdx.x * 256 + threadIdx.x;
    __shared__ float es[1024];
    for (int i = threadIdx.x; i < 1024; i += 256) {
        float e = emb[b * 1024 + i];
        es[i] = siluf(e);
    }
    __syncthreads();
    float acc = eb[n];
    #pragma unroll 4
    for (int kk = 0; kk < 1024; kk++)
        acc += es[kk] * W[(size_t)kk * 2048 + n];
    ss[b * 2048 + n] = acc;
}

// ---------------- LN2 + modulation + silu (fp16 y in, fp16 permuted out) ----------------
__global__ __launch_bounds__(256)
void ln2_kernel(const __half* __restrict__ y, const float* __restrict__ g,
                const float* __restrict__ bb, const float* __restrict__ ss,
                __half* __restrict__ h)
{
    const int row = blockIdx.x;
    const int b = row >> 12;
    const __half* yr = y + (size_t)row * Dd;
    float2 raw = *(const float2*)(yr + threadIdx.x * 4);
    const __half2* hp = (const __half2*)&raw;
    float2 p01 = __half22float2(hp[0]), p23 = __half22float2(hp[1]);
    float4 xv = make_float4(p01.x, p01.y, p23.x, p23.y);
    float s  = xv.x + xv.y + xv.z + xv.w;
    float s2 = xv.x*xv.x + xv.y*xv.y + xv.z*xv.z + xv.w*xv.w;

    __shared__ float sh1[8], sh2[8], bc[2];
    s = warpSum(s); s2 = warpSum(s2);
    int w = threadIdx.x >> 5;
    if ((threadIdx.x & 31) == 0) { sh1[w] = s; sh2[w] = s2; }
    __syncthreads();
    if (threadIdx.x == 0) {
        float a = 0.f, c = 0.f;
        #pragma unroll
        for (int i = 0; i < 8; i++) { a += sh1[i]; c += sh2[i]; }
        bc[0] = a; bc[1] = c;
    }
    __syncthreads();
    float mu  = bc[0] * (1.0f / Dd);
    float var = bc[1] * (1.0f / Dd) - mu * mu;
    float inv = rsqrtf(var + 1e-5f);

    int d = threadIdx.x * 4;
    float4 gv = *(const float4*)(g + d);
    float4 bv = *(const float4*)(bb + d);
    float4 sc = *(const float4*)(ss + b * 2048 + d);
    float4 sf = *(const float4*)(ss + b * 2048 + 1024 + d);
    float o0 = siluf(((xv.x - mu) * inv * gv.x + bv.x) * (1.0f + sc.x) + sf.x);
    float o1 = siluf(((xv.y - mu) * inv * gv.y + bv.y) * (1.0f + sc.y) + sf.y);
    float o2 = siluf(((xv.z - mu) * inv * gv.z + bv.z) * (1.0f + sc.z) + sf.z);
    float o3 = siluf(((xv.w - mu) * inv * gv.w + bv.w) * (1.0f + sc.w) + sf.w);
    __half2 u0 = __float22half2_rn(make_float2(o0, o1));
    __half2 u1 = __float22half2_rn(make_float2(o2, o3));
    __half* op = h + (size_t)row * Dd;
    *(__half2*)(op + pos16(d))     = u0;
    *(__half2*)(op + pos16(d + 2)) = u1;
}

// ---------------- launch ----------------
extern "C" void kernel_launch(void* const* d_in, const int* in_sizes, int n_in,
                              void* d_out, int out_size)
{
    const float* x        = (const float*)d_in[0];
    const float* emb      = (const float*)d_in[1];
    const float* gate_msa = (const float*)d_in[2];
    const float* norm_g   = (const float*)d_in[3];
    const float* norm_b   = (const float*)d_in[4];
    const float* Wq       = (const float*)d_in[5];
    const float* bq       = (const float*)d_in[6];
    const float* Wk       = (const float*)d_in[7];
    const float* bk       = (const float*)d_in[8];
    const float* Wv       = (const float*)d_in[9];
    const float* bv       = (const float*)d_in[10];
    const float* emb_W    = (const float*)d_in[11];
    const float* emb_b    = (const float*)d_in[12];
    const float* sn_g     = (const float*)d_in[13];
    const float* sn_b     = (const float*)d_in[14];
    const float* out_W    = (const float*)d_in[15];
    const float* out_b    = (const float*)d_in[16];
    float* out = (float*)d_out;

    __half *xnh, *hh, *wth, *q, *k, *v, *y;
    float *ctxp, *ctx, *ss, *cm, *cs;
    cudaGetSymbolAddress((void**)&xnh,  g_xnh);
    cudaGetSymbolAddress((void**)&hh,   g_hh);
    cudaGetSymbolAddress((void**)&wth,  g_wth);
    cudaGetSymbolAddress((void**)&q,    g_q);
    cudaGetSymbolAddress((void**)&k,    g_k);
    cudaGetSymbolAddress((void**)&v,    g_v);
    cudaGetSymbolAddress((void**)&y,    g_y);
    cudaGetSymbolAddress((void**)&ctxp, g_ctxp);
    cudaGetSymbolAddress((void**)&ctx,  g_ctx);
    cudaGetSymbolAddress((void**)&ss,   g_ss);
    cudaGetSymbolAddress((void**)&cm,   g_cm);
    cudaGetSymbolAddress((void**)&cs,   g_cs);

    cudaFuncSetAttribute(qkv_gemm, cudaFuncAttributeMaxDynamicSharedMemorySize, GSMEM);
    cudaFuncSetAttribute(out_gemm, cudaFuncAttributeMaxDynamicSharedMemorySize, GSMEM);

    // weight transposes (all -> fp16 pair-permuted)
    transpose_round4<<<dim3(32, 32, 4), dim3(32, 8)>>>(Wq, Wk, Wv, out_W, wth);

    // 1. LayerNorm -> fp16 (pair-permuted)
    ln1_kernel<<<Mm, 256>>>(x, norm_g, norm_b, xnh);

    // 2. FUSED Q/K/V projection (fp16 in/out)
    qkv_gemm<<<dim3(24, Mm / 128), 256, GSMEM>>>(xnh, wth, bq, bk, bv, q, k, v);

    // 3-4. context with ONLINE temporal softmax + exact combine
    ctx_kernel<<<dim3(Bb * Hh, CCH), 256>>>(k, v, ctxp, cm, cs);
    ctx_reduce<<<Bb * Hh, 256>>>(ctxp, cm, cs, ctx);

    // 5. y = softmax(q) @ ctx (fp16 q in, fp16 y out)
    y_kernel<<<dim3(Bb * Hh, Tt / 256), 256>>>(q, ctx, y);

    // 6. emb MLP
    emb_kernel<<<dim3(8, Bb), 256>>>(emb, emb_W, emb_b, ss);

    // 7. LN2 + modulation + silu (fp16 in/out, pair-permuted)
    ln2_kernel<<<Mm, 256>>>(y, sn_g, sn_b, ss, hh);

    // 8. out projection + residual epilogue (fp16 m16n8k16)
    out_gemm<<<dim3(8, Mm / 128), 256, GSMEM>>>(hh, wth + 3 * Dd * Dd, out_b, out, x, gate_msa);
}

// round 16
// speedup vs baseline: 1.0182x; 1.0182x over previous
#include <cuda_runtime.h>
#include <cuda_fp16.h>
#include <math.h>
#include <cstdint>

// Problem constants
#define Bb   4
#define Tt   4096
#define Dd   1024
#define Hh   16
#define DH   64
#define Mm   (Bb*Tt)          // 16384 rows
#define NELEM (Mm*Dd)
#define CCH  16               // ctx T-chunks (wave-quantization fix)

// ---------------- scratch (device globals; no allocation allowed) -------------
__device__ __half g_xnh[NELEM];           // ln1 out, fp16, pair-permuted
__device__ __half g_hh [NELEM];           // ln2 out, fp16, pair-permuted
__device__ __half g_wth[4*Dd*Dd];         // Wq|Wk|Wv|out_W transposed, fp16, pair-permuted
__device__ __half g_q  [NELEM];
__device__ __half g_k  [NELEM];
__device__ __half g_v  [NELEM];
__device__ __half g_y  [NELEM];
__device__ float g_ctxp[CCH*Bb*Hh*DH*DH];
__device__ float g_cm [CCH*Bb*Hh*DH];
__device__ float g_cs [CCH*Bb*Hh*DH];
__device__ float g_ctx[Bb*Hh*DH*DH];
__device__ float g_ss [Bb*2*Dd];

__host__ __device__ __forceinline__ int pos16(int k) {
    int p = (k >> 1) & 7;
    int slot = 2 * (p & 3) + (p >> 2);
    return (k & ~15) | (slot * 2) | (k & 1);
}

// ---------------- helpers ----------------
__device__ __forceinline__ float warpSum(float v) {
    #pragma unroll
    for (int o = 16; o > 0; o >>= 1) v += __shfl_xor_sync(0xffffffffu, v, o);
    return v;
}
__device__ __forceinline__ float siluf(float v) { return v / (1.0f + __expf(-v)); }

#define CP_ASYNC16(dst, src) \
    asm volatile("cp.async.cg.shared.global [%0], [%1], 16;" :: "r"(dst), "l"(src))
#define CP_COMMIT() asm volatile("cp.async.commit_group;" ::: "memory")
#define CP_WAIT(n)  asm volatile("cp.async.wait_group %0;" :: "n"(n) : "memory")

__device__ __forceinline__ uint32_t smem_u32(const void* p) {
    uint32_t a;
    asm("{ .reg .u64 t; cvta.to.shared.u64 t, %1; cvt.u32.u64 %0, t; }" : "=r"(a) : "l"(p));
    return a;
}

__device__ __forceinline__ void lds64(uint32_t addr, uint32_t& r0, uint32_t& r1) {
    asm volatile("ld.shared.v2.b32 {%0,%1}, [%2];" : "=r"(r0), "=r"(r1) : "r"(addr));
}

__device__ __forceinline__ void mma_fp16(float* c, uint32_t a0, uint32_t a1, uint32_t a2,
                                         uint32_t a3, uint32_t b0, uint32_t b1) {
    asm volatile(
        "mma.sync.aligned.m16n8k16.row.col.f32.f16.f16.f32 "
        "{%0,%1,%2,%3}, {%4,%5,%6,%7}, {%8,%9}, {%0,%1,%2,%3};"
        : "+f"(c[0]), "+f"(c[1]), "+f"(c[2]), "+f"(c[3])
        : "r"(a0), "r"(a1), "r"(a2), "r"(a3), "r"(b0), "r"(b1));
}

// ================= fp16 GEMM core constants =================
#define BM 128
#define BN 128
#define BKB 64
#define LDB 80
#define BSTGB (BM*LDB)
#define NITB (Dd/BKB)
#define GSMEM 81920

// ================= fp16 fused QKV GEMM (fp16 outputs) =================
__global__ void __launch_bounds__(256, 2)
qkv_gemm(const __half* __restrict__ A, const __half* __restrict__ Bt,
         const float* __restrict__ bias_q, const float* __restrict__ bias_k,
         const float* __restrict__ bias_v,
         __half* __restrict__ Cq, __half* __restrict__ Ck, __half* __restrict__ Cv)
{
    extern __shared__ float sm[];

    const int tid  = threadIdx.x;
    const int wid  = tid >> 5;
    const int lane = tid & 31;
    const int g    = lane >> 2;
    const int tig  = lane & 3;
    const int wm   = wid >> 1;
    const int wn   = wid & 1;
    const int cRow = blockIdx.y * BM;

    const int sel = blockIdx.x >> 3;
    const float* bias = (sel == 0) ? bias_q : (sel == 1) ? bias_k : bias_v;
    __half* C         = (sel == 0) ? Cq     : (sel == 1) ? Ck     : Cv;
    const int cCol = (blockIdx.x & 7) * BN;

    const int prow = tid >> 3;
    const int pch  = tid & 7;
    const uint32_t smBase = smem_u32(sm);
    const uint32_t sA0 = smBase + (uint32_t)(prow * LDB + pch * 8) * 2;
    const uint32_t sB0 = sA0 + 2u * BSTGB * 2;
    const __half* gA = A  + (size_t)(cRow + prow) * Dd + pch * 8;
    const __half* gB = Bt + (size_t)(blockIdx.x * BN + prow) * Dd + pch * 8;

    #define LOAD_STAGE(it) do { \
        int _s = (it) & 1; int _k0 = (it) * BKB; \
        uint32_t _sa = sA0 + (uint32_t)(_s * BSTGB) * 2; \
        uint32_t _sb = sB0 + (uint32_t)(_s * BSTGB) * 2; \
        _Pragma("unroll") \
        for (int _p = 0; _p < 4; _p++) { \
            CP_ASYNC16(_sa + _p * 32 * LDB * 2, gA + (size_t)_p * 32 * Dd + _k0); \
            CP_ASYNC16(_sb + _p * 32 * LDB * 2, gB + (size_t)_p * 32 * Dd + _k0); \
        } \
        CP_COMMIT(); \
    } while (0)

    LOAD_STAGE(0);

    float acc[2][8][4] = {};

    const uint32_t aW = smBase + (uint32_t)((wm*32 + g) * LDB) * 2 + tig * 8;
    const uint32_t bW = smBase + (uint32_t)(2 * BSTGB + (wn*64 + g) * LDB) * 2 + tig * 8;

    for (int it = 0; it < NITB; ++it) {
        CP_WAIT(0);
        __syncthreads();
        if (it + 1 < NITB) LOAD_STAGE(it + 1);

        const uint32_t so = (uint32_t)((it & 1) * BSTGB * 2);
        const uint32_t aS = aW + so;
        const uint32_t bS = bW + so;
        #pragma unroll
        for (int ks = 0; ks < 4; ks++) {
            const uint32_t kb = ks * 32;
            uint32_t a[2][4];
            lds64(aS + kb,                 a[0][0], a[0][2]);
            lds64(aS + 8*LDB*2 + kb,       a[0][1], a[0][3]);
            lds64(aS + 16*LDB*2 + kb,      a[1][0], a[1][2]);
            lds64(aS + 24*LDB*2 + kb,      a[1][1], a[1][3]);
            #pragma unroll
            for (int nt = 0; nt < 8; nt++) {
                uint32_t b0, b1;
                lds64(bS + nt*8*LDB*2 + kb, b0, b1);
                mma_fp16(acc[0][nt], a[0][0], a[0][1], a[0][2], a[0][3], b0, b1);
                mma_fp16(acc[1][nt], a[1][0], a[1][1], a[1][2], a[1][3], b0, b1);
            }
        }
    }

    #pragma unroll
    for (int mt = 0; mt < 2; mt++) {
        const int r0 = cRow + wm*32 + mt*16 + g;
        const int r1 = r0 + 8;
        #pragma unroll
        for (int nt = 0; nt < 8; nt++) {
            const int c0 = cCol + wn*64 + nt*8 + tig*2;
            float bx = bias[c0], by = bias[c0+1];
            __half2 u0 = __float22half2_rn(make_float2(acc[mt][nt][0] + bx, acc[mt][nt][1] + by));
            __half2 u1 = __float22half2_rn(make_float2(acc[mt][nt][2] + bx, acc[mt][nt][3] + by));
            *(__half2*)(C + (size_t)r0 * Dd + c0) = u0;
            *(__half2*)(C + (size_t)r1 * Dd + c0) = u1;
        }
    }
    #undef LOAD_STAGE
}

// ================= fp16 out-projection GEMM (+ residual epilogue, fp32 out) =================
__global__ void __launch_bounds__(256, 2)
out_gemm(const __half* __restrict__ A, const __half* __restrict__ Bt,
         const float* __restrict__ bias, float* __restrict__ C,
         const float* __restrict__ resid, const float* __restrict__ gate)
{
    extern __shared__ float sm[];

    const int tid  = threadIdx.x;
    const int wid  = tid >> 5;
    const int lane = tid & 31;
    const int g    = lane >> 2;
    const int tig  = lane & 3;
    const int wm   = wid >> 1;
    const int wn   = wid & 1;
    const int cRow = blockIdx.y * BM;
    const int cCol = blockIdx.x * BN;

    const int prow = tid >> 3;
    const int pch  = tid & 7;
    const uint32_t smBase = smem_u32(sm);
    const uint32_t sA0 = smBase + (uint32_t)(prow * LDB + pch * 8) * 2;
    const uint32_t sB0 = sA0 + 2u * BSTGB * 2;
    const __half* gA = A  + (size_t)(cRow + prow) * Dd + pch * 8;
    const __half* gB = Bt + (size_t)(cCol + prow) * Dd + pch * 8;

    #define LOAD_STAGE(it) do { \
        int _s = (it) & 1; int _k0 = (it) * BKB; \
        uint32_t _sa = sA0 + (uint32_t)(_s * BSTGB) * 2; \
        uint32_t _sb = sB0 + (uint32_t)(_s * BSTGB) * 2; \
        _Pragma("unroll") \
        for (int _p = 0; _p < 4; _p++) { \
            CP_ASYNC16(_sa + _p * 32 * LDB * 2, gA + (size_t)_p * 32 * Dd + _k0); \
            CP_ASYNC16(_sb + _p * 32 * LDB * 2, gB + (size_t)_p * 32 * Dd + _k0); \
        } \
        CP_COMMIT(); \
    } while (0)

    LOAD_STAGE(0);

    float acc[2][8][4] = {};

    const uint32_t aW = smBase + (uint32_t)((wm*32 + g) * LDB) * 2 + tig * 8;
    const uint32_t bW = smBase + (uint32_t)(2 * BSTGB + (wn*64 + g) * LDB) * 2 + tig * 8;

    for (int it = 0; it < NITB; ++it) {
        CP_WAIT(0);
        __syncthreads();
        if (it + 1 < NITB) LOAD_STAGE(it + 1);

        const uint32_t so = (uint32_t)((it & 1) * BSTGB * 2);
        const uint32_t aS = aW + so;
        const uint32_t bS = bW + so;
        #pragma unroll
        for (int ks = 0; ks < 4; ks++) {
            const uint32_t kb = ks * 32;
            uint32_t a[2][4];
            lds64(aS + kb,                 a[0][0], a[0][2]);
            lds64(aS + 8*LDB*2 + kb,       a[0][1], a[0][3]);
            lds64(aS + 16*LDB*2 + kb,      a[1][0], a[1][2]);
            lds64(aS + 24*LDB*2 + kb,      a[1][1], a[1][3]);
            #pragma unroll
            for (int nt = 0; nt < 8; nt++) {
                uint32_t b0, b1;
                lds64(bS + nt*8*LDB*2 + kb, b0, b1);
                mma_fp16(acc[0][nt], a[0][0], a[0][1], a[0][2], a[0][3], b0, b1);
                mma_fp16(acc[1][nt], a[1][0], a[1][1], a[1][2], a[1][3], b0, b1);
            }
        }
    }

    const int bb = cRow >> 12;
    #pragma unroll
    for (int mt = 0; mt < 2; mt++) {
        const int r0 = cRow + wm*32 + mt*16 + g;
        const int r1 = r0 + 8;
        #pragma unroll
        for (int nt = 0; nt < 8; nt++) {
            const int c0 = cCol + wn*64 + nt*8 + tig*2;
            float bx = bias[c0], by = bias[c0+1];
            float gx = gate[bb*Dd + c0], gy = gate[bb*Dd + c0 + 1];
            float2 rA = *(const float2*)(resid + (size_t)r0 * Dd + c0);
            float2 rB = *(const float2*)(resid + (size_t)r1 * Dd + c0);
            float2 v0, v1;
            v0.x = rA.x + gx * (acc[mt][nt][0] + bx);
            v0.y = rA.y + gy * (acc[mt][nt][1] + by);
            v1.x = rB.x + gx * (acc[mt][nt][2] + bx);
            v1.y = rB.y + gy * (acc[mt][nt][3] + by);
            *(float2*)(C + (size_t)r0 * Dd + c0) = v0;
            *(float2*)(C + (size_t)r1 * Dd + c0) = v1;
        }
    }
    #undef LOAD_STAGE
}

// ---------------- weight transposes: all 4 -> fp16, pair-permuted ----------------
__global__ __launch_bounds__(256)
void transpose_round4(const float* __restrict__ W0, const float* __restrict__ W1,
                      const float* __restrict__ W2, const float* __restrict__ W3,
                      __half* __restrict__ Wth)
{
    const float* W = (blockIdx.z == 0) ? W0 : (blockIdx.z == 1) ? W1 :
                     (blockIdx.z == 2) ? W2 : W3;
    __half* out = Wth + (size_t)blockIdx.z * Dd * Dd;

    __shared__ float t[32][33];
    int x = blockIdx.x * 32 + threadIdx.x;
    int y = blockIdx.y * 32 + threadIdx.y;
    #pragma unroll
    for (int j = 0; j < 32; j += 8)
        t[threadIdx.y + j][threadIdx.x] = W[(size_t)(y + j) * Dd + x];
    __syncthreads();
    int xo = blockIdx.y * 32 + threadIdx.x;
    int yo = blockIdx.x * 32 + threadIdx.y;
    int xp = pos16(xo);
    #pragma unroll
    for (int j = 0; j < 32; j += 8)
        out[(size_t)(yo + j) * Dd + xp] = __float2half(t[threadIdx.x][threadIdx.y + j]);
}

// ---------------- LayerNorm 1: x -> xn (fp16, pair-permuted store) ----------------
__global__ __launch_bounds__(256)
void ln1_kernel(const float* __restrict__ x, const float* __restrict__ g,
                const float* __restrict__ b, __half* __restrict__ out)
{
    const int row = blockIdx.x;
    const float* xr = x + (size_t)row * Dd;
    float4 xv = *(const float4*)(xr + threadIdx.x * 4);
    float s  = xv.x + xv.y + xv.z + xv.w;
    float s2 = xv.x*xv.x + xv.y*xv.y + xv.z*xv.z + xv.w*xv.w;

    __shared__ float sh1[8], sh2[8], bc[2];
    s = warpSum(s); s2 = warpSum(s2);
    int w = threadIdx.x >> 5;
    if ((threadIdx.x & 31) == 0) { sh1[w] = s; sh2[w] = s2; }
    __syncthreads();
    if (threadIdx.x == 0) {
        float a = 0.f, c = 0.f;
        #pragma unroll
        for (int i = 0; i < 8; i++) { a += sh1[i]; c += sh2[i]; }
        bc[0] = a; bc[1] = c;
    }
    __syncthreads();
    float mu  = bc[0] * (1.0f / Dd);
    float var = bc[1] * (1.0f / Dd) - mu * mu;
    float inv = rsqrtf(var + 1e-5f);

    int d = threadIdx.x * 4;
    float4 gv = *(const float4*)(g + d);
    float4 bv = *(const float4*)(b + d);
    float o0 = (xv.x - mu) * inv * gv.x + bv.x;
    float o1 = (xv.y - mu) * inv * gv.y + bv.y;
    float o2 = (xv.z - mu) * inv * gv.z + bv.z;
    float o3 = (xv.w - mu) * inv * gv.w + bv.w;
    __half2 u0 = __float22half2_rn(make_float2(o0, o1));
    __half2 u1 = __float22half2_rn(make_float2(o2, o3));
    __half* ob = out + (size_t)row * Dd;
    *(__half2*)(ob + pos16(d))     = u0;
    *(__half2*)(ob + pos16(d + 2)) = u1;
}

// ---------------- ctx: online temporal softmax (r14 core, CCH=16) --------
__global__ __launch_bounds__(256)
void ctx_kernel(const __half* __restrict__ k, const __half* __restrict__ v,
                float* __restrict__ ctxp, float* __restrict__ cm, float* __restrict__ cs)
{
    int bh = blockIdx.x;
    int b = bh >> 4, h = bh & 15;
    __shared__ float ks[64][64];
    __shared__ float vs[64][64];
    __shared__ float m_sh[64], s_sh[64], f_sh[64];
    __shared__ float part[4][64];
    int tr = threadIdx.x >> 4, tc = threadIdx.x & 15;
    const int rd = threadIdx.x & 63;
    const int qt = threadIdx.x >> 6;

    if (threadIdx.x < 64) { m_sh[threadIdx.x] = -INFINITY; s_sh[threadIdx.x] = 0.0f; }

    float acc[4][4] = {};
    int tbase = blockIdx.y * (Tt / CCH);
    for (int tt0 = 0; tt0 < Tt / CCH; tt0 += 64) {
        __syncthreads();
        for (int i = threadIdx.x; i < 64 * 16; i += 256) {
            int t  = i >> 4;
            int c4 = (i & 15) * 4;
            size_t off = ((size_t)((b * Tt + tbase + tt0 + t)) * Hh + h) * DH + c4;
            float2 kraw = *(const float2*)(k + off);
            float2 vraw = *(const float2*)(v + off);
            const __half2* kh = (const __half2*)&kraw;
            const __half2* vh = (const __half2*)&vraw;
            float2 k01 = __half22float2(kh[0]), k23 = __half22float2(kh[1]);
            float2 v01 = __half22float2(vh[0]), v23 = __half22float2(vh[1]);
            ks[t][c4+0] = k01.x; ks[t][c4+1] = k01.y;
            ks[t][c4+2] = k23.x; ks[t][c4+3] = k23.y;
            vs[t][c4+0] = v01.x; vs[t][c4+1] = v01.y;
            vs[t][c4+2] = v23.x; vs[t][c4+3] = v23.y;
        }
        __syncthreads();
        {
            float tm = -INFINITY;
            #pragma unroll
            for (int t = 0; t < 16; t++) tm = fmaxf(tm, ks[qt * 16 + t][rd]);
            part[qt][rd] = tm;
        }
        __syncthreads();
        if (threadIdx.x < 64) {
            int d = threadIdx.x;
            float tm = fmaxf(fmaxf(part[0][d], part[1][d]), fmaxf(part[2][d], part[3][d]));
            float mn = fmaxf(m_sh[d], tm);
            f_sh[d] = __expf(m_sh[d] - mn);
            m_sh[d] = mn;
        }
        __syncthreads();
        {
            float md = m_sh[rd];
            float csum = 0.0f;
            #pragma unroll
            for (int t = 0; t < 16; t++) {
                float e = __expf(ks[qt * 16 + t][rd] - md);
                ks[qt * 16 + t][rd] = e;
                csum += e;
            }
            part[qt][rd] = csum;
        }
        __syncthreads();
        if (threadIdx.x < 64) {
            int d = threadIdx.x;
            s_sh[d] = s_sh[d] * f_sh[d] +
                      ((part[0][d] + part[1][d]) + (part[2][d] + part[3][d]));
        }
        float f0 = f_sh[tr*4+0], f1 = f_sh[tr*4+1];
        float f2 = f_sh[tr*4+2], f3 = f_sh[tr*4+3];
        #pragma unroll
        for (int j = 0; j < 4; j++) {
            acc[0][j] *= f0; acc[1][j] *= f1; acc[2][j] *= f2; acc[3][j] *= f3;
        }
        #pragma unroll 8
        for (int t = 0; t < 64; t++) {
            float rk[4], rv[4];
            #pragma unroll
            for (int i = 0; i < 4; i++) rk[i] = ks[t][tr * 4 + i];
            #pragma unroll
            for (int j = 0; j < 4; j++) rv[j] = vs[t][tc * 4 + j];
            #pragma unroll
            for (int i = 0; i < 4; i++)
                #pragma unroll
                for (int j = 0; j < 4; j++)
                    acc[i][j] += rk[i] * rv[j];
        }
    }
    __syncthreads();
    float* c = ctxp + (size_t)blockIdx.y * (Bb*Hh*DH*DH) + (size_t)bh * (DH * DH);
    #pragma unroll
    for (int i = 0; i < 4; i++)
        #pragma unroll
        for (int j = 0; j < 4; j++)
            c[(tr * 4 + i) * DH + tc * 4 + j] = acc[i][j];
    if (threadIdx.x < 64) {
        int idx = blockIdx.y * (Bb*Hh*DH) + bh * DH + threadIdx.x;
        cm[idx] = m_sh[threadIdx.x];
        cs[idx] = s_sh[threadIdx.x];
    }
}

// global combine over CCH chunks
__global__ __launch_bounds__(256)
void ctx_reduce(const float* __restrict__ p, const float* __restrict__ cm,
                const float* __restrict__ cs, float* __restrict__ ctx)
{
    int bh = blockIdx.x;
    __shared__ float ef[CCH][64];
    __shared__ float Sinv[64];
    int tid = threadIdx.x;
    if (tid < 64) {
        float mx = -INFINITY;
        #pragma unroll
        for (int c = 0; c < CCH; c++)
            mx = fmaxf(mx, cm[c * (Bb*Hh*DH) + bh * DH + tid]);
        float S = 0.0f;
        #pragma unroll
        for (int c = 0; c < CCH; c++) {
            float e = __expf(cm[c * (Bb*Hh*DH) + bh * DH + tid] - mx);
            ef[c][tid] = e;
            S += cs[c * (Bb*Hh*DH) + bh * DH + tid] * e;
        }
        Sinv[tid] = 1.0f / S;
    }
    __syncthreads();
    for (int i = tid; i < DH * DH; i += 256) {
        int d = i >> 6;
        float s = 0.0f;
        #pragma unroll
        for (int c = 0; c < CCH; c++)
            s += p[(size_t)c * (Bb*Hh*DH*DH) + (size_t)bh * (DH*DH) + i] * ef[c][d];
        ctx[(size_t)bh * (DH*DH) + i] = s * Sinv[d];
    }
}

// ---------------- y = softmax(q) @ ctx  (fp16 q in, fp16 y out) ----------------
__global__ __launch_bounds__(256)
void y_kernel(const __half* __restrict__ q, const float* __restrict__ ctx,
              __half* __restrict__ y)
{
    int bh = blockIdx.x;
    int b = bh >> 4, h = bh & 15;
    __shared__ float cs[DH * DH];
    for (int i = threadIdx.x; i < 1024; i += 256)
        *(float4*)&cs[i * 4] = *(const float4*)(ctx + (size_t)bh * (DH * DH) + i * 4);
    __syncthreads();

    int t = blockIdx.y * 256 + threadIdx.x;
    size_t off = ((size_t)(b * Tt + t) * Hh + h) * DH;
    const float4* qr4 = (const float4*)(q + off);

    float4 qv[16];
    #pragma unroll
    for (int j = 0; j < 8; j++) {
        float4 raw = qr4[j];
        const __half2* hp = (const __half2*)&raw;
        float2 a = __half22float2(hp[0]), bb2 = __half22float2(hp[1]);
        float2 c = __half22float2(hp[2]), dd2 = __half22float2(hp[3]);
        qv[2*j]   = make_float4(a.x, a.y, bb2.x, bb2.y);
        qv[2*j+1] = make_float4(c.x, c.y, dd2.x, dd2.y);
    }
    float m = -INFINITY;
    #pragma unroll
    for (int j = 0; j < 16; j++)
        m = fmaxf(m, fmaxf(fmaxf(qv[j].x, qv[j].y), fmaxf(qv[j].z, qv[j].w)));
    float sum = 0.f;
    #pragma unroll
    for (int j = 0; j < 16; j++) {
        qv[j].x = __expf(qv[j].x - m); qv[j].y = __expf(qv[j].y - m);
        qv[j].z = __expf(qv[j].z - m); qv[j].w = __expf(qv[j].w - m);
        sum += qv[j].x + qv[j].y + qv[j].z + qv[j].w;
    }
    float sinv = 1.0f / sum;

    float4 acc[16];
    #pragma unroll
    for (int j = 0; j < 16; j++) acc[j] = make_float4(0.f, 0.f, 0.f, 0.f);

    #pragma unroll 4
    for (int j4 = 0; j4 < 16; j4++) {
        int d0 = j4 * 4;
        #pragma unroll
        for (int dd = 0; dd < 4; dd++) {
            float qd = ((dd == 0) ? qv[j4].x : (dd == 1) ? qv[j4].y :
                        (dd == 2) ? qv[j4].z : qv[j4].w) * sinv;
            const float4* crow = (const float4*)(cs + (d0 + dd) * DH);
            #pragma unroll
            for (int j = 0; j < 16; j++) {
                float4 c = crow[j];
                acc[j].x += qd * c.x;
                acc[j].y += qd * c.y;
                acc[j].z += qd * c.z;
                acc[j].w += qd * c.w;
            }
        }
    }
    float4* yr = (float4*)(y + off);
    #pragma unroll
    for (int j = 0; j < 8; j++) {
        float4 raw;
        __half2* hp = (__half2*)&raw;
        hp[0] = __float22half2_rn(make_float2(acc[2*j].x,   acc[2*j].y));
        hp[1] = __float22half2_rn(make_float2(acc[2*j].z,   acc[2*j].w));
        hp[2] = __float22half2_rn(make_float2(acc[2*j+1].x, acc[2*j+1].y));
        hp[3] = __float22half2_rn(make_float2(acc[2*j+1].z, acc[2*j+1].w));
        yr[j] = raw;
    }
}

// ---------------- emb MLP ----------------
__global__ __launch_bounds__(256)
void emb_kernel(const float* __restrict__ emb, const float* __restrict__ W,
                const float* __restrict__ eb, float* __restrict__ ss)
{
    int b = blockIdx.y;
    int n = blockIdx.x * 256 + threadIdx.x;
    __shared__ float es[1024];
    for (int i = threadIdx.x; i < 1024; i += 256) {
        float e = emb[b * 1024 + i];
        es[i] = siluf(e);
    }
    __syncthreads();
    float acc = eb[n];
    #pragma unroll 4
    for (int kk = 0; kk < 1024; kk++)
        acc += es[kk] * W[(size_t)kk * 2048 + n];
    ss[b * 2048 + n] = acc;
}

// ---------------- LN2 + modulation + silu (fp16 y in, fp16 permuted out) ----------------
__global__ __launch_bounds__(256)
void ln2_kernel(const __half* __restrict__ y, const float* __restrict__ g,
                const float* __restrict__ bb, const float* __restrict__ ss,
                __half* __restrict__ h)
{
    const int row = blockIdx.x;
    const int b = row >> 12;
    const __half* yr = y + (size_t)row * Dd;
    float2 raw = *(const float2*)(yr + threadIdx.x * 4);
    const __half2* hp = (const __half2*)&raw;
    float2 p01 = __half22float2(hp[0]), p23 = __half22float2(hp[1]);
    float4 xv = make_float4(p01.x, p01.y, p23.x, p23.y);
    float s  = xv.x + xv.y + xv.z + xv.w;
    float s2 = xv.x*xv.x + xv.y*xv.y + xv.z*xv.z + xv.w*xv.w;

    __shared__ float sh1[8], sh2[8], bc[2];
    s = warpSum(s); s2 = warpSum(s2);
    int w = threadIdx.x >> 5;
    if ((threadIdx.x & 31) == 0) { sh1[w] = s; sh2[w] = s2; }
    __syncthreads();
    if (threadIdx.x == 0) {
        float a = 0.f, c = 0.f;
        #pragma unroll
        for (int i = 0; i < 8; i++) { a += sh1[i]; c += sh2[i]; }
        bc[0] = a; bc[1] = c;
    }
    __syncthreads();
    float mu  = bc[0] * (1.0f / Dd);
    float var = bc[1] * (1.0f / Dd) - mu * mu;
    float inv = rsqrtf(var + 1e-5f);

    int d = threadIdx.x * 4;
    float4 gv = *(const float4*)(g + d);
    float4 bv = *(const float4*)(bb + d);
    float4 sc = *(const float4*)(ss + b * 2048 + d);
    float4 sf = *(const float4*)(ss + b * 2048 + 1024 + d);
    float o0 = siluf(((xv.x - mu) * inv * gv.x + bv.x) * (1.0f + sc.x) + sf.x);
    float o1 = siluf(((xv.y - mu) * inv * gv.y + bv.y) * (1.0f + sc.y) + sf.y);
    float o2 = siluf(((xv.z - mu) * inv * gv.z + bv.z) * (1.0f + sc.z) + sf.z);
    float o3 = siluf(((xv.w - mu) * inv * gv.w + bv.w) * (1.0f + sc.w) + sf.w);
    __half2 u0 = __float22half2_rn(make_float2(o0, o1));
    __half2 u1 = __float22half2_rn(make_float2(o2, o3));
    __half* op = h + (size_t)row * Dd;
    *(__half2*)(op + pos16(d))     = u0;
    *(__half2*)(op + pos16(d + 2)) = u1;
}

// ---------------- launch ----------------
extern "C" void kernel_launch(void* const* d_in, const int* in_sizes, int n_in,
                              void* d_out, int out_size)
{
    const float* x        = (const float*)d_in[0];
    const float* emb      = (const float*)d_in[1];
    const float* gate_msa = (const float*)d_in[2];
    const float* norm_g   = (const float*)d_in[3];
    const float* norm_b   = (const float*)d_in[4];
    const float* Wq       = (const float*)d_in[5];
    const float* bq       = (const float*)d_in[6];
    const float* Wk       = (const float*)d_in[7];
    const float* bk       = (const float*)d_in[8];
    const float* Wv       = (const float*)d_in[9];
    const float* bv       = (const float*)d_in[10];
    const float* emb_W    = (const float*)d_in[11];
    const float* emb_b    = (const float*)d_in[12];
    const float* sn_g     = (const float*)d_in[13];
    const float* sn_b     = (const float*)d_in[14];
    const float* out_W    = (const float*)d_in[15];
    const float* out_b    = (const float*)d_in[16];
    float* out = (float*)d_out;

    __half *xnh, *hh, *wth, *q, *k, *v, *y;
    float *ctxp, *ctx, *ss, *cm, *cs;
    cudaGetSymbolAddress((void**)&xnh,  g_xnh);
    cudaGetSymbolAddress((void**)&hh,   g_hh);
    cudaGetSymbolAddress((void**)&wth,  g_wth);
    cudaGetSymbolAddress((void**)&q,    g_q);
    cudaGetSymbolAddress((void**)&k,    g_k);
    cudaGetSymbolAddress((void**)&v,    g_v);
    cudaGetSymbolAddress((void**)&y,    g_y);
    cudaGetSymbolAddress((void**)&ctxp, g_ctxp);
    cudaGetSymbolAddress((void**)&ctx,  g_ctx);
    cudaGetSymbolAddress((void**)&ss,   g_ss);
    cudaGetSymbolAddress((void**)&cm,   g_cm);
    cudaGetSymbolAddress((void**)&cs,   g_cs);

    cudaFuncSetAttribute(qkv_gemm, cudaFuncAttributeMaxDynamicSharedMemorySize, GSMEM);
    cudaFuncSetAttribute(out_gemm, cudaFuncAttributeMaxDynamicSharedMemorySize, GSMEM);

    // weight transposes (all -> fp16 pair-permuted)
    transpose_round4<<<dim3(32, 32, 4), dim3(32, 8)>>>(Wq, Wk, Wv, out_W, wth);

    // 1. LayerNorm -> fp16 (pair-permuted)
    ln1_kernel<<<Mm, 256>>>(x, norm_g, norm_b, xnh);

    // 2. FUSED Q/K/V projection (fp16 in/out)
    qkv_gemm<<<dim3(24, Mm / 128), 256, GSMEM>>>(xnh, wth, bq, bk, bv, q, k, v);

    // 3-4. context with ONLINE temporal softmax + exact combine (CCH=16)
    ctx_kernel<<<dim3(Bb * Hh, CCH), 256>>>(k, v, ctxp, cm, cs);
    ctx_reduce<<<Bb * Hh, 256>>>(ctxp, cm, cs, ctx);

    // 5. y = softmax(q) @ ctx (fp16 q in, fp16 y out)
    y_kernel<<<dim3(Bb * Hh, Tt / 256), 256>>>(q, ctx, y);

    // 6. emb MLP
    emb_kernel<<<dim3(8, Bb), 256>>>(emb, emb_W, emb_b, ss);

    // 7. LN2 + modulation + silu (fp16 in/out, pair-permuted)
    ln2_kernel<<<Mm, 256>>>(y, sn_g, sn_b, ss, hh);

    // 8. out projection + residual epilogue (fp16 m16n8k16)
    out_gemm<<<dim3(8, Mm / 128), 256, GSMEM>>>(hh, wth + 3 * Dd * Dd, out_b, out, x, gate_msa);
}

// round 17
// speedup vs baseline: 1.1160x; 1.0960x over previous
#include <cuda_runtime.h>
#include <cuda_fp16.h>
#include <math.h>
#include <cstdint>

// Problem constants
#define Bb   4
#define Tt   4096
#define Dd   1024
#define Hh   16
#define DH   64
#define Mm   (Bb*Tt)          // 16384 rows
#define NELEM (Mm*Dd)
#define CCH  16               // ctx T-chunks

// ---------------- scratch (device globals; no allocation allowed) -------------
__device__ __half g_xnh[NELEM];           // ln1 out, fp16, plain [row,K]
__device__ __half g_hh [NELEM];           // ln2 out, fp16, plain [row,K]
__device__ __half g_wth[4*Dd*Dd];         // Wq|Wk|Wv|out_W transposed [N,K], fp16
__device__ __half g_q  [NELEM];
__device__ __half g_k  [NELEM];
__device__ __half g_v  [NELEM];
__device__ __half g_y  [NELEM];
__device__ float g_ctxp[CCH*Bb*Hh*DH*DH];
__device__ float g_cm [CCH*Bb*Hh*DH];
__device__ float g_cs [CCH*Bb*Hh*DH];
__device__ float g_ctx[Bb*Hh*DH*DH];
__device__ float g_ss [Bb*2*Dd];

// ---------------- helpers ----------------
__device__ __forceinline__ float warpSum(float v) {
    #pragma unroll
    for (int o = 16; o > 0; o >>= 1) v += __shfl_xor_sync(0xffffffffu, v, o);
    return v;
}
__device__ __forceinline__ float siluf(float v) { return v / (1.0f + __expf(-v)); }

#define CP_ASYNC16(dst, src) \
    asm volatile("cp.async.cg.shared.global [%0], [%1], 16;" :: "r"(dst), "l"(src))
#define CP_COMMIT() asm volatile("cp.async.commit_group;" ::: "memory")
#define CP_WAIT(n)  asm volatile("cp.async.wait_group %0;" :: "n"(n) : "memory")

__device__ __forceinline__ uint32_t smem_u32(const void* p) {
    uint32_t a;
    asm("{ .reg .u64 t; cvta.to.shared.u64 t, %1; cvt.u32.u64 %0, t; }" : "=r"(a) : "l"(p));
    return a;
}

__device__ __forceinline__ void ldm4(uint32_t addr, uint32_t& r0, uint32_t& r1,
                                     uint32_t& r2, uint32_t& r3) {
    asm volatile("ldmatrix.sync.aligned.m8n8.x4.shared.b16 {%0,%1,%2,%3}, [%4];"
        : "=r"(r0), "=r"(r1), "=r"(r2), "=r"(r3) : "r"(addr));
}

__device__ __forceinline__ void mma_fp16(float* c, uint32_t a0, uint32_t a1, uint32_t a2,
                                         uint32_t a3, uint32_t b0, uint32_t b1) {
    asm volatile(
        "mma.sync.aligned.m16n8k16.row.col.f32.f16.f16.f32 "
        "{%0,%1,%2,%3}, {%4,%5,%6,%7}, {%8,%9}, {%0,%1,%2,%3};"
        : "+f"(c[0]), "+f"(c[1]), "+f"(c[2]), "+f"(c[3])
        : "r"(a0), "r"(a1), "r"(a2), "r"(a3), "r"(b0), "r"(b1));
}

// ================= fp16 GEMM core (ldmatrix + XOR swizzle) =================
// smem row = 128 B (64 halfs = one k-tile). Swizzle: chunk ^= row&7 (16B units).
// Stage = 128 rows * 128 B = 16 KB. Layout: A0 A1 B0 B1 = 64 KB.
#define BM 128
#define BN 128
#define STG  16384
#define NITB 16               // 1024 / 64
#define GSMEM 65536

// ================= fp16 fused QKV GEMM (fp16 outputs) =================
__global__ void __launch_bounds__(256, 2)
qkv_gemm(const __half* __restrict__ A, const __half* __restrict__ Bt,
         const float* __restrict__ bias_q, const float* __restrict__ bias_k,
         const float* __restrict__ bias_v,
         __half* __restrict__ Cq, __half* __restrict__ Ck, __half* __restrict__ Cv)
{
    extern __shared__ float sm[];

    const int tid  = threadIdx.x;
    const int wid  = tid >> 5;
    const int lane = tid & 31;
    const int g    = lane >> 2;
    const int tig  = lane & 3;
    const int wm   = wid >> 1;
    const int wn   = wid & 1;
    const int cRow = blockIdx.y * BM;

    const int sel = blockIdx.x >> 3;
    const float* bias = (sel == 0) ? bias_q : (sel == 1) ? bias_k : bias_v;
    __half* C         = (sel == 0) ? Cq     : (sel == 1) ? Ck     : Cv;
    const int cCol = (blockIdx.x & 7) * BN;

    // producer: 256 threads, rows prow+32p, 16B chunk pch (swizzled)
    const int prow = tid >> 3;
    const int pch  = tid & 7;
    const uint32_t smBase = smem_u32(sm);
    const uint32_t swz = (uint32_t)((pch ^ (prow & 7)) << 4);
    const uint32_t dA0 = smBase + (uint32_t)prow * 128 + swz;
    const uint32_t dB0 = dA0 + 2u * STG;
    const __half* gA = A  + (size_t)(cRow + prow) * Dd + pch * 8;
    const __half* gB = Bt + (size_t)(blockIdx.x * BN + prow) * Dd + pch * 8;

    #define LOAD_STAGE(it) do { \
        uint32_t _so = ((it) & 1) * STG; int _k0 = (it) * 64; \
        _Pragma("unroll") \
        for (int _p = 0; _p < 4; _p++) { \
            CP_ASYNC16(dA0 + _so + _p * 32 * 128, gA + (size_t)_p * 32 * Dd + _k0); \
            CP_ASYNC16(dB0 + _so + _p * 32 * 128, gB + (size_t)_p * 32 * Dd + _k0); \
        } \
        CP_COMMIT(); \
    } while (0)

    LOAD_STAGE(0);

    float acc[2][8][4] = {};

    // ldmatrix lane addressing
    const int row_off = (lane & 7) | (((lane >> 3) & 1) << 3);  // 0..15
    const int cx  = lane >> 4;                                   // 0/1 (k8 select)
    const int par = row_off & 7;
    const uint32_t aB0 = smBase + (uint32_t)(wm * 32 + row_off) * 128;
    const uint32_t aB1 = aB0 + 16 * 128;
    uint32_t bB[4];
    #pragma unroll
    for (int p = 0; p < 4; p++)
        bB[p] = smBase + 2u * STG + (uint32_t)(wn * 64 + p * 16 + row_off) * 128;

    for (int it = 0; it < NITB; ++it) {
        CP_WAIT(0);
        __syncthreads();
        if (it + 1 < NITB) LOAD_STAGE(it + 1);

        const uint32_t so = (uint32_t)((it & 1) * STG);
        #pragma unroll
        for (int ks = 0; ks < 4; ks++) {
            const uint32_t xoff = (uint32_t)(((2 * ks + cx) ^ par) << 4);
            uint32_t a0[4], a1[4];
            ldm4(aB0 + so + xoff, a0[0], a0[1], a0[2], a0[3]);
            ldm4(aB1 + so + xoff, a1[0], a1[1], a1[2], a1[3]);
            #pragma unroll
            for (int p = 0; p < 4; p++) {
                uint32_t r0, r1, r2, r3;
                ldm4(bB[p] + so + xoff, r0, r1, r2, r3);
                mma_fp16(acc[0][2*p],   a0[0], a0[1], a0[2], a0[3], r0, r2);
                mma_fp16(acc[0][2*p+1], a0[0], a0[1], a0[2], a0[3], r1, r3);
                mma_fp16(acc[1][2*p],   a1[0], a1[1], a1[2], a1[3], r0, r2);
                mma_fp16(acc[1][2*p+1], a1[0], a1[1], a1[2], a1[3], r1, r3);
            }
        }
    }

    #pragma unroll
    for (int mt = 0; mt < 2; mt++) {
        const int r0 = cRow + wm*32 + mt*16 + g;
        const int r1 = r0 + 8;
        #pragma unroll
        for (int nt = 0; nt < 8; nt++) {
            const int c0 = cCol + wn*64 + nt*8 + tig*2;
            float bx = bias[c0], by = bias[c0+1];
            __half2 u0 = __float22half2_rn(make_float2(acc[mt][nt][0] + bx, acc[mt][nt][1] + by));
            __half2 u1 = __float22half2_rn(make_float2(acc[mt][nt][2] + bx, acc[mt][nt][3] + by));
            *(__half2*)(C + (size_t)r0 * Dd + c0) = u0;
            *(__half2*)(C + (size_t)r1 * Dd + c0) = u1;
        }
    }
    #undef LOAD_STAGE
}

// ================= fp16 out-projection GEMM (+ residual epilogue, fp32 out) =================
__global__ void __launch_bounds__(256, 2)
out_gemm(const __half* __restrict__ A, const __half* __restrict__ Bt,
         const float* __restrict__ bias, float* __restrict__ C,
         const float* __restrict__ resid, const float* __restrict__ gate)
{
    extern __shared__ float sm[];

    const int tid  = threadIdx.x;
    const int wid  = tid >> 5;
    const int lane = tid & 31;
    const int g    = lane >> 2;
    const int tig  = lane & 3;
    const int wm   = wid >> 1;
    const int wn   = wid & 1;
    const int cRow = blockIdx.y * BM;
    const int cCol = blockIdx.x * BN;

    const int prow = tid >> 3;
    const int pch  = tid & 7;
    const uint32_t smBase = smem_u32(sm);
    const uint32_t swz = (uint32_t)((pch ^ (prow & 7)) << 4);
    const uint32_t dA0 = smBase + (uint32_t)prow * 128 + swz;
    const uint32_t dB0 = dA0 + 2u * STG;
    const __half* gA = A  + (size_t)(cRow + prow) * Dd + pch * 8;
    const __half* gB = Bt + (size_t)(cCol + prow) * Dd + pch * 8;

    #define LOAD_STAGE(it) do { \
        uint32_t _so = ((it) & 1) * STG; int _k0 = (it) * 64; \
        _Pragma("unroll") \
        for (int _p = 0; _p < 4; _p++) { \
            CP_ASYNC16(dA0 + _so + _p * 32 * 128, gA + (size_t)_p * 32 * Dd + _k0); \
            CP_ASYNC16(dB0 + _so + _p * 32 * 128, gB + (size_t)_p * 32 * Dd + _k0); \
        } \
        CP_COMMIT(); \
    } while (0)

    LOAD_STAGE(0);

    float acc[2][8][4] = {};

    const int row_off = (lane & 7) | (((lane >> 3) & 1) << 3);
    const int cx  = lane >> 4;
    const int par = row_off & 7;
    const uint32_t aB0 = smBase + (uint32_t)(wm * 32 + row_off) * 128;
    const uint32_t aB1 = aB0 + 16 * 128;
    uint32_t bB[4];
    #pragma unroll
    for (int p = 0; p < 4; p++)
        bB[p] = smBase + 2u * STG + (uint32_t)(wn * 64 + p * 16 + row_off) * 128;

    for (int it = 0; it < NITB; ++it) {
        CP_WAIT(0);
        __syncthreads();
        if (it + 1 < NITB) LOAD_STAGE(it + 1);

        const uint32_t so = (uint32_t)((it & 1) * STG);
        #pragma unroll
        for (int ks = 0; ks < 4; ks++) {
            const uint32_t xoff = (uint32_t)(((2 * ks + cx) ^ par) << 4);
            uint32_t a0[4], a1[4];
            ldm4(aB0 + so + xoff, a0[0], a0[1], a0[2], a0[3]);
            ldm4(aB1 + so + xoff, a1[0], a1[1], a1[2], a1[3]);
            #pragma unroll
            for (int p = 0; p < 4; p++) {
                uint32_t r0, r1, r2, r3;
                ldm4(bB[p] + so + xoff, r0, r1, r2, r3);
                mma_fp16(acc[0][2*p],   a0[0], a0[1], a0[2], a0[3], r0, r2);
                mma_fp16(acc[0][2*p+1], a0[0], a0[1], a0[2], a0[3], r1, r3);
                mma_fp16(acc[1][2*p],   a1[0], a1[1], a1[2], a1[3], r0, r2);
                mma_fp16(acc[1][2*p+1], a1[0], a1[1], a1[2], a1[3], r1, r3);
            }
        }
    }

    const int bb = cRow >> 12;
    #pragma unroll
    for (int mt = 0; mt < 2; mt++) {
        const int r0 = cRow + wm*32 + mt*16 + g;
        const int r1 = r0 + 8;
        #pragma unroll
        for (int nt = 0; nt < 8; nt++) {
            const int c0 = cCol + wn*64 + nt*8 + tig*2;
            float bx = bias[c0], by = bias[c0+1];
            float gx = gate[bb*Dd + c0], gy = gate[bb*Dd + c0 + 1];
            float2 rA = *(const float2*)(resid + (size_t)r0 * Dd + c0);
            float2 rB = *(const float2*)(resid + (size_t)r1 * Dd + c0);
            float2 v0, v1;
            v0.x = rA.x + gx * (acc[mt][nt][0] + bx);
            v0.y = rA.y + gy * (acc[mt][nt][1] + by);
            v1.x = rB.x + gx * (acc[mt][nt][2] + bx);
            v1.y = rB.y + gy * (acc[mt][nt][3] + by);
            *(float2*)(C + (size_t)r0 * Dd + c0) = v0;
            *(float2*)(C + (size_t)r1 * Dd + c0) = v1;
        }
    }
    #undef LOAD_STAGE
}

// ---------------- weight transposes: all 4 -> fp16 [N,K] plain ----------------
__global__ __launch_bounds__(256)
void transpose_round4(const float* __restrict__ W0, const float* __restrict__ W1,
                      const float* __restrict__ W2, const float* __restrict__ W3,
                      __half* __restrict__ Wth)
{
    const float* W = (blockIdx.z == 0) ? W0 : (blockIdx.z == 1) ? W1 :
                     (blockIdx.z == 2) ? W2 : W3;
    __half* out = Wth + (size_t)blockIdx.z * Dd * Dd;

    __shared__ float t[32][33];
    int x = blockIdx.x * 32 + threadIdx.x;
    int y = blockIdx.y * 32 + threadIdx.y;
    #pragma unroll
    for (int j = 0; j < 32; j += 8)
        t[threadIdx.y + j][threadIdx.x] = W[(size_t)(y + j) * Dd + x];
    __syncthreads();
    int xo = blockIdx.y * 32 + threadIdx.x;   // k
    int yo = blockIdx.x * 32 + threadIdx.y;   // n
    #pragma unroll
    for (int j = 0; j < 32; j += 8)
        out[(size_t)(yo + j) * Dd + xo] = __float2half(t[threadIdx.x][threadIdx.y + j]);
}

// ---------------- LayerNorm 1: x -> xn (fp16 plain) ----------------
__global__ __launch_bounds__(256)
void ln1_kernel(const float* __restrict__ x, const float* __restrict__ g,
                const float* __restrict__ b, __half* __restrict__ out)
{
    const int row = blockIdx.x;
    const float* xr = x + (size_t)row * Dd;
    float4 xv = *(const float4*)(xr + threadIdx.x * 4);
    float s  = xv.x + xv.y + xv.z + xv.w;
    float s2 = xv.x*xv.x + xv.y*xv.y + xv.z*xv.z + xv.w*xv.w;

    __shared__ float sh1[8], sh2[8], bc[2];
    s = warpSum(s); s2 = warpSum(s2);
    int w = threadIdx.x >> 5;
    if ((threadIdx.x & 31) == 0) { sh1[w] = s; sh2[w] = s2; }
    __syncthreads();
    if (threadIdx.x == 0) {
        float a = 0.f, c = 0.f;
        #pragma unroll
        for (int i = 0; i < 8; i++) { a += sh1[i]; c += sh2[i]; }
        bc[0] = a; bc[1] = c;
    }
    __syncthreads();
    float mu  = bc[0] * (1.0f / Dd);
    float var = bc[1] * (1.0f / Dd) - mu * mu;
    float inv = rsqrtf(var + 1e-5f);

    int d = threadIdx.x * 4;
    float4 gv = *(const float4*)(g + d);
    float4 bv = *(const float4*)(b + d);
    float o0 = (xv.x - mu) * inv * gv.x + bv.x;
    float o1 = (xv.y - mu) * inv * gv.y + bv.y;
    float o2 = (xv.z - mu) * inv * gv.z + bv.z;
    float o3 = (xv.w - mu) * inv * gv.w + bv.w;
    __half2 u[2];
    u[0] = __float22half2_rn(make_float2(o0, o1));
    u[1] = __float22half2_rn(make_float2(o2, o3));
    *(float2*)(out + (size_t)row * Dd + d) = *(float2*)u;
}

// ---------------- ctx: online temporal softmax (r16 core, CCH=16) --------
__global__ __launch_bounds__(256)
void ctx_kernel(const __half* __restrict__ k, const __half* __restrict__ v,
                float* __restrict__ ctxp, float* __restrict__ cm, float* __restrict__ cs)
{
    int bh = blockIdx.x;
    int b = bh >> 4, h = bh & 15;
    __shared__ float ks[64][64];
    __shared__ float vs[64][64];
    __shared__ float m_sh[64], s_sh[64], f_sh[64];
    __shared__ float part[4][64];
    int tr = threadIdx.x >> 4, tc = threadIdx.x & 15;
    const int rd = threadIdx.x & 63;
    const int qt = threadIdx.x >> 6;

    if (threadIdx.x < 64) { m_sh[threadIdx.x] = -INFINITY; s_sh[threadIdx.x] = 0.0f; }

    float acc[4][4] = {};
    int tbase = blockIdx.y * (Tt / CCH);
    for (int tt0 = 0; tt0 < Tt / CCH; tt0 += 64) {
        __syncthreads();
        for (int i = threadIdx.x; i < 64 * 16; i += 256) {
            int t  = i >> 4;
            int c4 = (i & 15) * 4;
            size_t off = ((size_t)((b * Tt + tbase + tt0 + t)) * Hh + h) * DH + c4;
            float2 kraw = *(const float2*)(k + off);
            float2 vraw = *(const float2*)(v + off);
            const __half2* kh = (const __half2*)&kraw;
            const __half2* vh = (const __half2*)&vraw;
            float2 k01 = __half22float2(kh[0]), k23 = __half22float2(kh[1]);
            float2 v01 = __half22float2(vh[0]), v23 = __half22float2(vh[1]);
            ks[t][c4+0] = k01.x; ks[t][c4+1] = k01.y;
            ks[t][c4+2] = k23.x; ks[t][c4+3] = k23.y;
            vs[t][c4+0] = v01.x; vs[t][c4+1] = v01.y;
            vs[t][c4+2] = v23.x; vs[t][c4+3] = v23.y;
        }
        __syncthreads();
        {
            float tm = -INFINITY;
            #pragma unroll
            for (int t = 0; t < 16; t++) tm = fmaxf(tm, ks[qt * 16 + t][rd]);
            part[qt][rd] = tm;
        }
        __syncthreads();
        if (threadIdx.x < 64) {
            int d = threadIdx.x;
            float tm = fmaxf(fmaxf(part[0][d], part[1][d]), fmaxf(part[2][d], part[3][d]));
            float mn = fmaxf(m_sh[d], tm);
            f_sh[d] = __expf(m_sh[d] - mn);
            m_sh[d] = mn;
        }
        __syncthreads();
        {
            float md = m_sh[rd];
            float csum = 0.0f;
            #pragma unroll
            for (int t = 0; t < 16; t++) {
                float e = __expf(ks[qt * 16 + t][rd] - md);
                ks[qt * 16 + t][rd] = e;
                csum += e;
            }
            part[qt][rd] = csum;
        }
        __syncthreads();
        if (threadIdx.x < 64) {
            int d = threadIdx.x;
            s_sh[d] = s_sh[d] * f_sh[d] +
                      ((part[0][d] + part[1][d]) + (part[2][d] + part[3][d]));
        }
        float f0 = f_sh[tr*4+0], f1 = f_sh[tr*4+1];
        float f2 = f_sh[tr*4+2], f3 = f_sh[tr*4+3];
        #pragma unroll
        for (int j = 0; j < 4; j++) {
            acc[0][j] *= f0; acc[1][j] *= f1; acc[2][j] *= f2; acc[3][j] *= f3;
        }
        #pragma unroll 8
        for (int t = 0; t < 64; t++) {
            float rk[4], rv[4];
            #pragma unroll
            for (int i = 0; i < 4; i++) rk[i] = ks[t][tr * 4 + i];
            #pragma unroll
            for (int j = 0; j < 4; j++) rv[j] = vs[t][tc * 4 + j];
            #pragma unroll
            for (int i = 0; i < 4; i++)
                #pragma unroll
                for (int j = 0; j < 4; j++)
                    acc[i][j] += rk[i] * rv[j];
        }
    }
    __syncthreads();
    float* c = ctxp + (size_t)blockIdx.y * (Bb*Hh*DH*DH) + (size_t)bh * (DH * DH);
    #pragma unroll
    for (int i = 0; i < 4; i++)
        #pragma unroll
        for (int j = 0; j < 4; j++)
            c[(tr * 4 + i) * DH + tc * 4 + j] = acc[i][j];
    if (threadIdx.x < 64) {
        int idx = blockIdx.y * (Bb*Hh*DH) + bh * DH + threadIdx.x;
        cm[idx] = m_sh[threadIdx.x];
        cs[idx] = s_sh[threadIdx.x];
    }
}

// global combine over CCH chunks
__global__ __launch_bounds__(256)
void ctx_reduce(const float* __restrict__ p, const float* __restrict__ cm,
                const float* __restrict__ cs, float* __restrict__ ctx)
{
    int bh = blockIdx.x;
    __shared__ float ef[CCH][64];
    __shared__ float Sinv[64];
    int tid = threadIdx.x;
    if (tid < 64) {
        float mx = -INFINITY;
        #pragma unroll
        for (int c = 0; c < CCH; c++)
            mx = fmaxf(mx, cm[c * (Bb*Hh*DH) + bh * DH + tid]);
        float S = 0.0f;
        #pragma unroll
        for (int c = 0; c < CCH; c++) {
            float e = __expf(cm[c * (Bb*Hh*DH) + bh * DH + tid] - mx);
            ef[c][tid] = e;
            S += cs[c * (Bb*Hh*DH) + bh * DH + tid] * e;
        }
        Sinv[tid] = 1.0f / S;
    }
    __syncthreads();
    for (int i = tid; i < DH * DH; i += 256) {
        int d = i >> 6;
        float s = 0.0f;
        #pragma unroll
        for (int c = 0; c < CCH; c++)
            s += p[(size_t)c * (Bb*Hh*DH*DH) + (size_t)bh * (DH*DH) + i] * ef[c][d];
        ctx[(size_t)bh * (DH*DH) + i] = s * Sinv[d];
    }
}

// ---------------- y = softmax(q) @ ctx  (fp16 q in, fp16 y out) ----------------
__global__ __launch_bounds__(256)
void y_kernel(const __half* __restrict__ q, const float* __restrict__ ctx,
              __half* __restrict__ y)
{
    int bh = blockIdx.x;
    int b = bh >> 4, h = bh & 15;
    __shared__ float cs[DH * DH];
    for (int i = threadIdx.x; i < 1024; i += 256)
        *(float4*)&cs[i * 4] = *(const float4*)(ctx + (size_t)bh * (DH * DH) + i * 4);
    __syncthreads();

    int t = blockIdx.y * 256 + threadIdx.x;
    size_t off = ((size_t)(b * Tt + t) * Hh + h) * DH;
    const float4* qr4 = (const float4*)(q + off);

    float4 qv[16];
    #pragma unroll
    for (int j = 0; j < 8; j++) {
        float4 raw = qr4[j];
        const __half2* hp = (const __half2*)&raw;
        float2 a = __half22float2(hp[0]), bb2 = __half22float2(hp[1]);
        float2 c = __half22float2(hp[2]), dd2 = __half22float2(hp[3]);
        qv[2*j]   = make_float4(a.x, a.y, bb2.x, bb2.y);
        qv[2*j+1] = make_float4(c.x, c.y, dd2.x, dd2.y);
    }
    float m = -INFINITY;
    #pragma unroll
    for (int j = 0; j < 16; j++)
        m = fmaxf(m, fmaxf(fmaxf(qv[j].x, qv[j].y), fmaxf(qv[j].z, qv[j].w)));
    float sum = 0.f;
    #pragma unroll
    for (int j = 0; j < 16; j++) {
        qv[j].x = __expf(qv[j].x - m); qv[j].y = __expf(qv[j].y - m);
        qv[j].z = __expf(qv[j].z - m); qv[j].w = __expf(qv[j].w - m);
        sum += qv[j].x + qv[j].y + qv[j].z + qv[j].w;
    }
    float sinv = 1.0f / sum;

    float4 acc[16];
    #pragma unroll
    for (int j = 0; j < 16; j++) acc[j] = make_float4(0.f, 0.f, 0.f, 0.f);

    #pragma unroll 4
    for (int j4 = 0; j4 < 16; j4++) {
        int d0 = j4 * 4;
        #pragma unroll
        for (int dd = 0; dd < 4; dd++) {
            float qd = ((dd == 0) ? qv[j4].x : (dd == 1) ? qv[j4].y :
                        (dd == 2) ? qv[j4].z : qv[j4].w) * sinv;
            const float4* crow = (const float4*)(cs + (d0 + dd) * DH);
            #pragma unroll
            for (int j = 0; j < 16; j++) {
                float4 c = crow[j];
                acc[j].x += qd * c.x;
                acc[j].y += qd * c.y;
                acc[j].z += qd * c.z;
                acc[j].w += qd * c.w;
            }
        }
    }
    float4* yr = (float4*)(y + off);
    #pragma unroll
    for (int j = 0; j < 8; j++) {
        float4 raw;
        __half2* hp = (__half2*)&raw;
        hp[0] = __float22half2_rn(make_float2(acc[2*j].x,   acc[2*j].y));
        hp[1] = __float22half2_rn(make_float2(acc[2*j].z,   acc[2*j].w));
        hp[2] = __float22half2_rn(make_float2(acc[2*j+1].x, acc[2*j+1].y));
        hp[3] = __float22half2_rn(make_float2(acc[2*j+1].z, acc[2*j+1].w));
        yr[j] = raw;
    }
}

// ---------------- emb MLP ----------------
__global__ __launch_bounds__(256)
void emb_kernel(const float* __restrict__ emb, const float* __restrict__ W,
                const float* __restrict__ eb, float* __restrict__ ss)
{
    int b = blockIdx.y;
    int n = blockIdx.x * 256 + threadIdx.x;
    __shared__ float es[1024];
    for (int i = threadIdx.x; i < 1024; i += 256) {
        float e = emb[b * 1024 + i];
        es[i] = siluf(e);
    }
    __syncthreads();
    float acc = eb[n];
    #pragma unroll 4
    for (int kk = 0; kk < 1024; kk++)
        acc += es[kk] * W[(size_t)kk * 2048 + n];
    ss[b * 2048 + n] = acc;
}

// ---------------- LN2 + modulation + silu (fp16 in, fp16 plain out) ----------------
__global__ __launch_bounds__(256)
void ln2_kernel(const __half* __restrict__ y, const float* __restrict__ g,
                const float* __restrict__ bb, const float* __restrict__ ss,
                __half* __restrict__ h)
{
    const int row = blockIdx.x;
    const int b = row >> 12;
    const __half* yr = y + (size_t)row * Dd;
    float2 raw = *(const float2*)(yr + threadIdx.x * 4);
    const __half2* hp = (const __half2*)&raw;
    float2 p01 = __half22float2(hp[0]), p23 = __half22float2(hp[1]);
    float4 xv = make_float4(p01.x, p01.y, p23.x, p23.y);
    float s  = xv.x + xv.y + xv.z + xv.w;
    float s2 = xv.x*xv.x + xv.y*xv.y + xv.z*xv.z + xv.w*xv.w;

    __shared__ float sh1[8], sh2[8], bc[2];
    s = warpSum(s); s2 = warpSum(s2);
    int w = threadIdx.x >> 5;
    if ((threadIdx.x & 31) == 0) { sh1[w] = s; sh2[w] = s2; }
    __syncthreads();
    if (threadIdx.x == 0) {
        float a = 0.f, c = 0.f;
        #pragma unroll
        for (int i = 0; i < 8; i++) { a += sh1[i]; c += sh2[i]; }
        bc[0] = a; bc[1] = c;
    }
    __syncthreads();
    float mu  = bc[0] * (1.0f / Dd);
    float var = bc[1] * (1.0f / Dd) - mu * mu;
    float inv = rsqrtf(var + 1e-5f);

    int d = threadIdx.x * 4;
    float4 gv = *(const float4*)(g + d);
    float4 bv = *(const float4*)(bb + d);
    float4 sc = *(const float4*)(ss + b * 2048 + d);
    float4 sf = *(const float4*)(ss + b * 2048 + 1024 + d);
    float o0 = siluf(((xv.x - mu) * inv * gv.x + bv.x) * (1.0f + sc.x) + sf.x);
    float o1 = siluf(((xv.y - mu) * inv * gv.y + bv.y) * (1.0f + sc.y) + sf.y);
    float o2 = siluf(((xv.z - mu) * inv * gv.z + bv.z) * (1.0f + sc.z) + sf.z);
    float o3 = siluf(((xv.w - mu) * inv * gv.w + bv.w) * (1.0f + sc.w) + sf.w);
    __half2 u[2];
    u[0] = __float22half2_rn(make_float2(o0, o1));
    u[1] = __float22half2_rn(make_float2(o2, o3));
    *(float2*)(h + (size_t)row * Dd + d) = *(float2*)u;
}

// ---------------- launch ----------------
extern "C" void kernel_launch(void* const* d_in, const int* in_sizes, int n_in,
                              void* d_out, int out_size)
{
    const float* x        = (const float*)d_in[0];
    const float* emb      = (const float*)d_in[1];
    const float* gate_msa = (const float*)d_in[2];
    const float* norm_g   = (const float*)d_in[3];
    const float* norm_b   = (const float*)d_in[4];
    const float* Wq       = (const float*)d_in[5];
    const float* bq       = (const float*)d_in[6];
    const float* Wk       = (const float*)d_in[7];
    const float* bk       = (const float*)d_in[8];
    const float* Wv       = (const float*)d_in[9];
    const float* bv       = (const float*)d_in[10];
    const float* emb_W    = (const float*)d_in[11];
    const float* emb_b    = (const float*)d_in[12];
    const float* sn_g     = (const float*)d_in[13];
    const float* sn_b     = (const float*)d_in[14];
    const float* out_W    = (const float*)d_in[15];
    const float* out_b    = (const float*)d_in[16];
    float* out = (float*)d_out;

    __half *xnh, *hh, *wth, *q, *k, *v, *y;
    float *ctxp, *ctx, *ss, *cm, *cs;
    cudaGetSymbolAddress((void**)&xnh,  g_xnh);
    cudaGetSymbolAddress((void**)&hh,   g_hh);
    cudaGetSymbolAddress((void**)&wth,  g_wth);
    cudaGetSymbolAddress((void**)&q,    g_q);
    cudaGetSymbolAddress((void**)&k,    g_k);
    cudaGetSymbolAddress((void**)&v,    g_v);
    cudaGetSymbolAddress((void**)&y,    g_y);
    cudaGetSymbolAddress((void**)&ctxp, g_ctxp);
    cudaGetSymbolAddress((void**)&ctx,  g_ctx);
    cudaGetSymbolAddress((void**)&ss,   g_ss);
    cudaGetSymbolAddress((void**)&cm,   g_cm);
    cudaGetSymbolAddress((void**)&cs,   g_cs);

    cudaFuncSetAttribute(qkv_gemm, cudaFuncAttributeMaxDynamicSharedMemorySize, GSMEM);
    cudaFuncSetAttribute(out_gemm, cudaFuncAttributeMaxDynamicSharedMemorySize, GSMEM);

    // weight transposes (all -> fp16 [N,K] plain)
    transpose_round4<<<dim3(32, 32, 4), dim3(32, 8)>>>(Wq, Wk, Wv, out_W, wth);

    // 1. LayerNorm -> fp16 plain
    ln1_kernel<<<Mm, 256>>>(x, norm_g, norm_b, xnh);

    // 2. FUSED Q/K/V projection (fp16, ldmatrix)
    qkv_gemm<<<dim3(24, Mm / 128), 256, GSMEM>>>(xnh, wth, bq, bk, bv, q, k, v);

    // 3-4. context with ONLINE temporal softmax + exact combine (CCH=16)
    ctx_kernel<<<dim3(Bb * Hh, CCH), 256>>>(k, v, ctxp, cm, cs);
    ctx_reduce<<<Bb * Hh, 256>>>(ctxp, cm, cs, ctx);

    // 5. y = softmax(q) @ ctx
    y_kernel<<<dim3(Bb * Hh, Tt / 256), 256>>>(q, ctx, y);

    // 6. emb MLP
    emb_kernel<<<dim3(8, Bb), 256>>>(emb, emb_W, emb_b, ss);

    // 7. LN2 + modulation + silu (fp16 plain)
    ln2_kernel<<<Mm, 256>>>(y, sn_g, sn_b, ss, hh);

    // 8. out projection + residual epilogue (fp16, ldmatrix)
    out_gemm<<<dim3(8, Mm / 128), 256, GSMEM>>>(hh, wth + 3 * Dd * Dd, out_b, out, x, gate_msa);
}